// round 1
// baseline (speedup 1.0000x reference)
#include <cuda_runtime.h>

#define HID 1024
#define NT  1024
#define NE  16
#define IT  512
#define IV  256
#define CAP 1024
#define NZ  32   // (modality * 16 + expert)

// ---------------- scratch (static __device__ globals: allowed) ----------------
__device__ int   g_cnt[NZ];
__device__ int   g_tok[NZ][CAP];
__device__ float g_wgt[NZ][CAP];
__device__ float g_act[NZ][CAP][IT];    // expert-MLP activations (64 MB)
__device__ float g_shact[NT][HID];      // shared-expert activations (4 MB)

// ---------------- K0: zero counters ----------------
__global__ void k_zero() {
    if (threadIdx.x < NZ) g_cnt[threadIdx.x] = 0;
}

// ---------------- K1: router (one block per token, 512 threads) ----------------
__global__ __launch_bounds__(512) void k_router(
    const float* __restrict__ x, const int* __restrict__ tt,
    const float* __restrict__ rwT, const float* __restrict__ bT,
    const float* __restrict__ rwV, const float* __restrict__ bV,
    float* __restrict__ out_logits)
{
    const int t   = blockIdx.x;
    const int mod = (tt[t] != 0) ? 1 : 0;
    const float* rw   = mod ? rwV : rwT;
    const float* bias = mod ? bV  : bT;

    __shared__ float xs[HID];
    __shared__ float lg[NE];
    const int tid = threadIdx.x;
    xs[tid]       = x[(size_t)t * HID + tid];
    xs[tid + 512] = x[(size_t)t * HID + tid + 512];
    __syncthreads();

    const int e = tid >> 5, lane = tid & 31;   // one warp per expert
    float s = 0.f;
    const float* w = rw + (size_t)e * HID;
    #pragma unroll 8
    for (int h = lane; h < HID; h += 32) s += xs[h] * w[h];
    #pragma unroll
    for (int o = 16; o; o >>= 1) s += __shfl_xor_sync(0xffffffffu, s, o);
    if (lane == 0) lg[e] = s;
    __syncthreads();

    if (tid < NE) out_logits[(size_t)t * NE + tid] = lg[tid];

    if (tid == 0) {
        float mx = lg[0];
        #pragma unroll
        for (int i = 1; i < NE; i++) mx = fmaxf(mx, lg[i]);
        float p[NE]; float sum = 0.f;
        #pragma unroll
        for (int i = 0; i < NE; i++) { p[i] = expf(lg[i] - mx); sum += p[i]; }
        const float inv = 1.f / sum;
        #pragma unroll
        for (int i = 0; i < NE; i++) p[i] *= inv;
        // top-2 on p + bias (lowest index wins ties, matching lax.top_k)
        int i1 = 0, i2 = -1; float s1 = -1e30f, s2 = -1e30f;
        #pragma unroll
        for (int i = 0; i < NE; i++) {
            float sc = p[i] + bias[i];
            if (sc > s1)      { s2 = s1; i2 = i1; s1 = sc; i1 = i; }
            else if (sc > s2) { s2 = sc; i2 = i; }
        }
        float w1 = p[i1], w2 = p[i2];
        const float ws = fmaxf(w1 + w2, 1e-12f);
        w1 /= ws; w2 /= ws;
        const int z1 = mod * 16 + i1, z2 = mod * 16 + i2;
        int a = atomicAdd(&g_cnt[z1], 1);
        g_tok[z1][a] = t; g_wgt[z1][a] = w1;
        int b = atomicAdd(&g_cnt[z2], 1);
        g_tok[z2][b] = t; g_wgt[z2][b] = w2;
    }
}

// Tiled-GEMM config: BM=64, BN=64, BK=16, 128 threads, 8x4 register tile.
// tx = tid & 15 (4 cols each), ty = tid >> 4 (8 rows each).

// ---------------- K2: shared experts, act = silu(x@Wg) * (x@Wu) ----------------
__global__ __launch_bounds__(128) void k_shared_gu(
    const float* __restrict__ x,
    const float* __restrict__ Wg, const float* __restrict__ Wu)
{
    __shared__ __align__(16) float As[16][64];
    __shared__ __align__(16) float Bg[16][64];
    __shared__ __align__(16) float Bu[16][64];
    const int tid = threadIdx.x;
    const int tx = tid & 15, ty = tid >> 4;
    const int row0 = blockIdx.y * 64, col0 = blockIdx.x * 64;
    float ag[8][4] = {}, au[8][4] = {};

    for (int k0 = 0; k0 < HID; k0 += 16) {
        #pragma unroll
        for (int p = 0; p < 2; p++) {
            int e0 = (tid + p * 128) * 4;
            int r = e0 >> 4, c = e0 & 15;
            float4 v = *(const float4*)&x[(size_t)(row0 + r) * HID + k0 + c];
            As[c + 0][r] = v.x; As[c + 1][r] = v.y; As[c + 2][r] = v.z; As[c + 3][r] = v.w;
        }
        #pragma unroll
        for (int p = 0; p < 2; p++) {
            int e0 = (tid + p * 128) * 4;
            int r = e0 >> 6, c = e0 & 63;
            *(float4*)&Bg[r][c] = *(const float4*)&Wg[(size_t)(k0 + r) * 1024 + col0 + c];
            *(float4*)&Bu[r][c] = *(const float4*)&Wu[(size_t)(k0 + r) * 1024 + col0 + c];
        }
        __syncthreads();
        #pragma unroll
        for (int kk = 0; kk < 16; kk++) {
            float a[8], bg[4], bu[4];
            *(float4*)&a[0] = *(float4*)&As[kk][ty * 8];
            *(float4*)&a[4] = *(float4*)&As[kk][ty * 8 + 4];
            *(float4*)bg = *(float4*)&Bg[kk][tx * 4];
            *(float4*)bu = *(float4*)&Bu[kk][tx * 4];
            #pragma unroll
            for (int i = 0; i < 8; i++)
                #pragma unroll
                for (int j = 0; j < 4; j++) {
                    ag[i][j] += a[i] * bg[j];
                    au[i][j] += a[i] * bu[j];
                }
        }
        __syncthreads();
    }
    #pragma unroll
    for (int i = 0; i < 8; i++)
        #pragma unroll
        for (int j = 0; j < 4; j++) {
            float g = ag[i][j];
            float sig = 1.f / (1.f + __expf(-g));
            g_shact[row0 + ty * 8 + i][col0 + tx * 4 + j] = g * sig * au[i][j];
        }
}

// ---------------- K3: out = shact @ shared_down (initializes d_out) ----------------
__global__ __launch_bounds__(128) void k_shared_down(
    const float* __restrict__ Wd, float* __restrict__ out)
{
    __shared__ __align__(16) float As[16][64];
    __shared__ __align__(16) float Bs[16][64];
    const int tid = threadIdx.x;
    const int tx = tid & 15, ty = tid >> 4;
    const int row0 = blockIdx.y * 64, col0 = blockIdx.x * 64;
    float acc[8][4] = {};

    for (int k0 = 0; k0 < HID; k0 += 16) {
        #pragma unroll
        for (int p = 0; p < 2; p++) {
            int e0 = (tid + p * 128) * 4;
            int r = e0 >> 4, c = e0 & 15;
            float4 v = *(const float4*)&g_shact[row0 + r][k0 + c];
            As[c + 0][r] = v.x; As[c + 1][r] = v.y; As[c + 2][r] = v.z; As[c + 3][r] = v.w;
        }
        #pragma unroll
        for (int p = 0; p < 2; p++) {
            int e0 = (tid + p * 128) * 4;
            int r = e0 >> 6, c = e0 & 63;
            *(float4*)&Bs[r][c] = *(const float4*)&Wd[(size_t)(k0 + r) * 1024 + col0 + c];
        }
        __syncthreads();
        #pragma unroll
        for (int kk = 0; kk < 16; kk++) {
            float a[8], b[4];
            *(float4*)&a[0] = *(float4*)&As[kk][ty * 8];
            *(float4*)&a[4] = *(float4*)&As[kk][ty * 8 + 4];
            *(float4*)b = *(float4*)&Bs[kk][tx * 4];
            #pragma unroll
            for (int i = 0; i < 8; i++)
                #pragma unroll
                for (int j = 0; j < 4; j++) acc[i][j] += a[i] * b[j];
        }
        __syncthreads();
    }
    #pragma unroll
    for (int i = 0; i < 8; i++)
        #pragma unroll
        for (int j = 0; j < 4; j++)
            out[(size_t)(row0 + ty * 8 + i) * HID + col0 + tx * 4 + j] = acc[i][j];
}

// ---------------- K4: expert gate_up (gathered rows), act -> g_act ----------------
__global__ __launch_bounds__(128) void k_expert_gu(
    const float* __restrict__ x,
    const float* __restrict__ t_gu, const float* __restrict__ v_gu)
{
    const int z = blockIdx.z;
    const int mod = z >> 4, e = z & 15;
    const int I = mod ? IV : IT;
    const int col0 = blockIdx.x * 64;
    if (col0 >= I) return;
    const int n = g_cnt[z];
    const int row0 = blockIdx.y * 64;
    if (row0 >= n) return;
    const float* W = mod ? (v_gu + (size_t)e * HID * 2 * IV)
                         : (t_gu + (size_t)e * HID * 2 * IT);
    const int ldw = 2 * I;

    __shared__ __align__(16) float As[16][64];
    __shared__ __align__(16) float Bg[16][64];
    __shared__ __align__(16) float Bu[16][64];
    __shared__ int toks[64];

    const int tid = threadIdx.x;
    const int tx = tid & 15, ty = tid >> 4;
    if (tid < 64) {
        int s = row0 + tid;
        toks[tid] = (s < n) ? g_tok[z][s] : 0;
    }
    __syncthreads();

    float ag[8][4] = {}, au[8][4] = {};
    for (int k0 = 0; k0 < HID; k0 += 16) {
        #pragma unroll
        for (int p = 0; p < 2; p++) {
            int e0 = (tid + p * 128) * 4;
            int r = e0 >> 4, c = e0 & 15;
            float4 v = *(const float4*)&x[(size_t)toks[r] * HID + k0 + c];
            As[c + 0][r] = v.x; As[c + 1][r] = v.y; As[c + 2][r] = v.z; As[c + 3][r] = v.w;
        }
        #pragma unroll
        for (int p = 0; p < 2; p++) {
            int e0 = (tid + p * 128) * 4;
            int r = e0 >> 6, c = e0 & 63;
            *(float4*)&Bg[r][c] = *(const float4*)&W[(size_t)(k0 + r) * ldw + col0 + c];
            *(float4*)&Bu[r][c] = *(const float4*)&W[(size_t)(k0 + r) * ldw + I + col0 + c];
        }
        __syncthreads();
        #pragma unroll
        for (int kk = 0; kk < 16; kk++) {
            float a[8], bg[4], bu[4];
            *(float4*)&a[0] = *(float4*)&As[kk][ty * 8];
            *(float4*)&a[4] = *(float4*)&As[kk][ty * 8 + 4];
            *(float4*)bg = *(float4*)&Bg[kk][tx * 4];
            *(float4*)bu = *(float4*)&Bu[kk][tx * 4];
            #pragma unroll
            for (int i = 0; i < 8; i++)
                #pragma unroll
                for (int j = 0; j < 4; j++) {
                    ag[i][j] += a[i] * bg[j];
                    au[i][j] += a[i] * bu[j];
                }
        }
        __syncthreads();
    }
    #pragma unroll
    for (int i = 0; i < 8; i++) {
        int slot = row0 + ty * 8 + i;
        if (slot < n) {
            #pragma unroll
            for (int j = 0; j < 4; j++) {
                float g = ag[i][j];
                float sig = 1.f / (1.f + __expf(-g));
                g_act[z][slot][col0 + tx * 4 + j] = g * sig * au[i][j];
            }
        }
    }
}

// ---------------- K5: expert down, scaled atomic scatter into out ----------------
__global__ __launch_bounds__(128) void k_expert_down(
    const float* __restrict__ t_dn, const float* __restrict__ v_dn,
    float* __restrict__ out)
{
    const int z = blockIdx.z;
    const int mod = z >> 4, e = z & 15;
    const int n = g_cnt[z];
    const int row0 = blockIdx.y * 64;
    if (row0 >= n) return;
    const int col0 = blockIdx.x * 64;
    const int I = mod ? IV : IT;
    const float* W = mod ? (v_dn + (size_t)e * IV * HID)
                         : (t_dn + (size_t)e * IT * HID);

    __shared__ __align__(16) float As[16][64];
    __shared__ __align__(16) float Bs[16][64];
    const int tid = threadIdx.x;
    const int tx = tid & 15, ty = tid >> 4;
    float acc[8][4] = {};

    for (int k0 = 0; k0 < I; k0 += 16) {
        #pragma unroll
        for (int p = 0; p < 2; p++) {
            int e0 = (tid + p * 128) * 4;
            int r = e0 >> 4, c = e0 & 15;
            float4 v = *(const float4*)&g_act[z][row0 + r][k0 + c];
            As[c + 0][r] = v.x; As[c + 1][r] = v.y; As[c + 2][r] = v.z; As[c + 3][r] = v.w;
        }
        #pragma unroll
        for (int p = 0; p < 2; p++) {
            int e0 = (tid + p * 128) * 4;
            int r = e0 >> 6, c = e0 & 63;
            *(float4*)&Bs[r][c] = *(const float4*)&W[(size_t)(k0 + r) * HID + col0 + c];
        }
        __syncthreads();
        #pragma unroll
        for (int kk = 0; kk < 16; kk++) {
            float a[8], b[4];
            *(float4*)&a[0] = *(float4*)&As[kk][ty * 8];
            *(float4*)&a[4] = *(float4*)&As[kk][ty * 8 + 4];
            *(float4*)b = *(float4*)&Bs[kk][tx * 4];
            #pragma unroll
            for (int i = 0; i < 8; i++)
                #pragma unroll
                for (int j = 0; j < 4; j++) acc[i][j] += a[i] * b[j];
        }
        __syncthreads();
    }
    #pragma unroll
    for (int i = 0; i < 8; i++) {
        int slot = row0 + ty * 8 + i;
        if (slot < n) {
            int t = g_tok[z][slot];
            float w = g_wgt[z][slot];
            #pragma unroll
            for (int j = 0; j < 4; j++)
                atomicAdd(&out[(size_t)t * HID + col0 + tx * 4 + j], w * acc[i][j]);
        }
    }
}

// ---------------- launch ----------------
extern "C" void kernel_launch(void* const* d_in, const int* in_sizes, int n_in,
                              void* d_out, int out_size)
{
    const float* x   = (const float*)d_in[0];
    const int*   tt  = (const int*)d_in[1];
    const float* trw = (const float*)d_in[2];
    const float* tb  = (const float*)d_in[3];
    const float* tgu = (const float*)d_in[4];
    const float* tdn = (const float*)d_in[5];
    const float* vrw = (const float*)d_in[6];
    const float* vb  = (const float*)d_in[7];
    const float* vgu = (const float*)d_in[8];
    const float* vdn = (const float*)d_in[9];
    const float* sg  = (const float*)d_in[10];
    const float* su  = (const float*)d_in[11];
    const float* sd  = (const float*)d_in[12];

    float* out        = (float*)d_out;
    float* out_logits = out + (size_t)NT * HID;

    k_zero<<<1, 32>>>();
    k_router<<<NT, 512>>>(x, tt, trw, tb, vrw, vb, out_logits);
    k_shared_gu<<<dim3(16, 16), 128>>>(x, sg, su);
    k_shared_down<<<dim3(16, 16), 128>>>(sd, out);
    k_expert_gu<<<dim3(8, 16, NZ), 128>>>(x, tgu, vgu);
    k_expert_down<<<dim3(16, 16, NZ), 128>>>(tdn, vdn, out);
}

// round 4
// speedup vs baseline: 1.7888x; 1.7888x over previous
#include <cuda_runtime.h>
#include <cstdint>

#define HID 1024
#define NT  1024
#define NE  16
#define IT  512
#define IV  256
#define CAP 1024
#define NZ  32   // (modality * 16 + expert)
#define BK  32
#define BKP 36   // BK + 4 pad: conflict-free quad access

// ---------------- scratch ----------------
__device__ int   g_cnt[NZ];
__device__ int   g_tok[NZ][CAP];
__device__ float g_wgt[NZ][CAP];
__device__ float g_act[NZ][CAP][IT];    // expert-MLP activations
__device__ float g_shact[NT][HID];      // shared-expert activations

__device__ __forceinline__ uint32_t f2tf32(float f) {
    uint32_t r; asm("cvt.rna.tf32.f32 %0, %1;" : "=r"(r) : "f"(f)); return r;
}

// m16n8k8 tf32 warp MMA, fp32 accumulate in-place
__device__ __forceinline__ void mma8(float* c, const uint32_t* a, uint32_t b0, uint32_t b1) {
    asm volatile(
        "mma.sync.aligned.m16n8k8.row.col.f32.tf32.tf32.f32 "
        "{%0,%1,%2,%3}, {%4,%5,%6,%7}, {%8,%9}, {%0,%1,%2,%3};"
        : "+f"(c[0]), "+f"(c[1]), "+f"(c[2]), "+f"(c[3])
        : "r"(a[0]), "r"(a[1]), "r"(a[2]), "r"(a[3]), "r"(b0), "r"(b1));
}

// ---------------- K0: zero counters ----------------
__global__ void k_zero() {
    if (threadIdx.x < NZ) g_cnt[threadIdx.x] = 0;
}

// ---------------- K1: router ----------------
__global__ __launch_bounds__(512) void k_router(
    const float* __restrict__ x, const int* __restrict__ tt,
    const float* __restrict__ rwT, const float* __restrict__ bT,
    const float* __restrict__ rwV, const float* __restrict__ bV,
    float* __restrict__ out_logits)
{
    const int t   = blockIdx.x;
    const int mod = (tt[t] != 0) ? 1 : 0;
    const float* rw   = mod ? rwV : rwT;
    const float* bias = mod ? bV  : bT;

    __shared__ float xs[HID];
    __shared__ float lg[NE];
    const int tid = threadIdx.x;
    xs[tid]       = x[(size_t)t * HID + tid];
    xs[tid + 512] = x[(size_t)t * HID + tid + 512];
    __syncthreads();

    const int e = tid >> 5, lane = tid & 31;
    float s = 0.f;
    const float* w = rw + (size_t)e * HID;
    #pragma unroll 8
    for (int h = lane; h < HID; h += 32) s += xs[h] * w[h];
    #pragma unroll
    for (int o = 16; o; o >>= 1) s += __shfl_xor_sync(0xffffffffu, s, o);
    if (lane == 0) lg[e] = s;
    __syncthreads();

    if (tid < NE) out_logits[(size_t)t * NE + tid] = lg[tid];

    if (tid == 0) {
        float mx = lg[0];
        #pragma unroll
        for (int i = 1; i < NE; i++) mx = fmaxf(mx, lg[i]);
        float p[NE]; float sum = 0.f;
        #pragma unroll
        for (int i = 0; i < NE; i++) { p[i] = expf(lg[i] - mx); sum += p[i]; }
        const float inv = 1.f / sum;
        #pragma unroll
        for (int i = 0; i < NE; i++) p[i] *= inv;
        int i1 = 0, i2 = -1; float s1 = -1e30f, s2 = -1e30f;
        #pragma unroll
        for (int i = 0; i < NE; i++) {
            float sc = p[i] + bias[i];
            if (sc > s1)      { s2 = s1; i2 = i1; s1 = sc; i1 = i; }
            else if (sc > s2) { s2 = sc; i2 = i; }
        }
        float w1 = p[i1], w2 = p[i2];
        const float ws = fmaxf(w1 + w2, 1e-12f);
        w1 /= ws; w2 /= ws;
        const int z1 = mod * 16 + i1, z2 = mod * 16 + i2;
        int a = atomicAdd(&g_cnt[z1], 1);
        g_tok[z1][a] = t; g_wgt[z1][a] = w1;
        int b = atomicAdd(&g_cnt[z2], 1);
        g_tok[z2][b] = t; g_wgt[z2][b] = w2;
    }
}

// ================= warp-MMA tf32 GEMM kernels =================
// 256 threads = 8 warps. Fragment maps per PTX m16n8k8:
//  A: a0(r=l>>2, c=l&3) a1(r+8) a2(c+4) a3(r+8,c+4); B(col): b0(k=l&3, n=l>>2) b1(k+4)
//  C: c0(r=l>>2, c=2*(l&3)) c1(c+1) c2(r+8) c3(r+8,c+1)

// ---- K2: shared gate/up: g_shact = silu(X@Wg)*(X@Wu). 128x64 tiles ----
__global__ __launch_bounds__(256) void k_sgu(
    const float* __restrict__ x,
    const float* __restrict__ Wg, const float* __restrict__ Wu)
{
    __shared__ uint32_t As[128][BKP];
    __shared__ uint32_t Bg[64][BKP];
    __shared__ uint32_t Bu[64][BKP];
    const int tid = threadIdx.x, wid = tid >> 5, lane = tid & 31;
    const int row0 = blockIdx.y * 128, col0 = blockIdx.x * 64;
    const int m0 = (wid >> 1) * 32, n0 = (wid & 1) * 32;
    const int ln = tid & 63, lk = (tid >> 6) * 8;
    float cg[2][4][4] = {}, cu[2][4][4] = {};

    for (int k0 = 0; k0 < HID; k0 += BK) {
        #pragma unroll
        for (int p = 0; p < 4; p++) {
            int idx = tid + p * 256;
            int r = idx >> 3, c4 = (idx & 7) * 4;
            float4 v = *(const float4*)&x[(size_t)(row0 + r) * HID + k0 + c4];
            uint4 tv = make_uint4(f2tf32(v.x), f2tf32(v.y), f2tf32(v.z), f2tf32(v.w));
            *(uint4*)&As[r][c4] = tv;
        }
        uint32_t vg[8], vu[8];
        #pragma unroll
        for (int j = 0; j < 8; j++) {
            vg[j] = f2tf32(Wg[(size_t)(k0 + lk + j) * HID + col0 + ln]);
            vu[j] = f2tf32(Wu[(size_t)(k0 + lk + j) * HID + col0 + ln]);
        }
        *(uint4*)&Bg[ln][lk]     = make_uint4(vg[0], vg[1], vg[2], vg[3]);
        *(uint4*)&Bg[ln][lk + 4] = make_uint4(vg[4], vg[5], vg[6], vg[7]);
        *(uint4*)&Bu[ln][lk]     = make_uint4(vu[0], vu[1], vu[2], vu[3]);
        *(uint4*)&Bu[ln][lk + 4] = make_uint4(vu[4], vu[5], vu[6], vu[7]);
        __syncthreads();
        #pragma unroll
        for (int kk = 0; kk < 4; kk++) {
            const int kc = kk * 8;
            uint32_t a[2][4];
            #pragma unroll
            for (int mt = 0; mt < 2; mt++) {
                int r = m0 + mt * 16 + (lane >> 2);
                a[mt][0] = As[r][kc + (lane & 3)];
                a[mt][1] = As[r + 8][kc + (lane & 3)];
                a[mt][2] = As[r][kc + (lane & 3) + 4];
                a[mt][3] = As[r + 8][kc + (lane & 3) + 4];
            }
            #pragma unroll
            for (int nt = 0; nt < 4; nt++) {
                int nb = n0 + nt * 8 + (lane >> 2);
                uint32_t g0 = Bg[nb][kc + (lane & 3)], g1 = Bg[nb][kc + (lane & 3) + 4];
                uint32_t u0 = Bu[nb][kc + (lane & 3)], u1 = Bu[nb][kc + (lane & 3) + 4];
                mma8(cg[0][nt], a[0], g0, g1);
                mma8(cg[1][nt], a[1], g0, g1);
                mma8(cu[0][nt], a[0], u0, u1);
                mma8(cu[1][nt], a[1], u0, u1);
            }
        }
        __syncthreads();
    }
    #pragma unroll
    for (int mt = 0; mt < 2; mt++)
        #pragma unroll
        for (int nt = 0; nt < 4; nt++)
            #pragma unroll
            for (int i = 0; i < 4; i++) {
                int r = row0 + m0 + mt * 16 + (lane >> 2) + ((i >= 2) ? 8 : 0);
                int cc = col0 + n0 + nt * 8 + (lane & 3) * 2 + (i & 1);
                float g = cg[mt][nt][i];
                g_shact[r][cc] = g / (1.f + __expf(-g)) * cu[mt][nt][i];
            }
}

// ---- K3: out = g_shact @ Wd (initializes d_out). 128x64 tiles ----
__global__ __launch_bounds__(256) void k_sdn(
    const float* __restrict__ Wd, float* __restrict__ out)
{
    __shared__ uint32_t As[128][BKP];
    __shared__ uint32_t Bs[64][BKP];
    const int tid = threadIdx.x, wid = tid >> 5, lane = tid & 31;
    const int row0 = blockIdx.y * 128, col0 = blockIdx.x * 64;
    const int m0 = (wid >> 1) * 32, n0 = (wid & 1) * 32;
    const int ln = tid & 63, lk = (tid >> 6) * 8;
    float c[2][4][4] = {};

    for (int k0 = 0; k0 < HID; k0 += BK) {
        #pragma unroll
        for (int p = 0; p < 4; p++) {
            int idx = tid + p * 256;
            int r = idx >> 3, c4 = (idx & 7) * 4;
            float4 v = *(const float4*)&g_shact[row0 + r][k0 + c4];
            *(uint4*)&As[r][c4] = make_uint4(f2tf32(v.x), f2tf32(v.y), f2tf32(v.z), f2tf32(v.w));
        }
        uint32_t vb[8];
        #pragma unroll
        for (int j = 0; j < 8; j++)
            vb[j] = f2tf32(Wd[(size_t)(k0 + lk + j) * HID + col0 + ln]);
        *(uint4*)&Bs[ln][lk]     = make_uint4(vb[0], vb[1], vb[2], vb[3]);
        *(uint4*)&Bs[ln][lk + 4] = make_uint4(vb[4], vb[5], vb[6], vb[7]);
        __syncthreads();
        #pragma unroll
        for (int kk = 0; kk < 4; kk++) {
            const int kc = kk * 8;
            uint32_t a[2][4];
            #pragma unroll
            for (int mt = 0; mt < 2; mt++) {
                int r = m0 + mt * 16 + (lane >> 2);
                a[mt][0] = As[r][kc + (lane & 3)];
                a[mt][1] = As[r + 8][kc + (lane & 3)];
                a[mt][2] = As[r][kc + (lane & 3) + 4];
                a[mt][3] = As[r + 8][kc + (lane & 3) + 4];
            }
            #pragma unroll
            for (int nt = 0; nt < 4; nt++) {
                int nb = n0 + nt * 8 + (lane >> 2);
                uint32_t b0 = Bs[nb][kc + (lane & 3)], b1 = Bs[nb][kc + (lane & 3) + 4];
                mma8(c[0][nt], a[0], b0, b1);
                mma8(c[1][nt], a[1], b0, b1);
            }
        }
        __syncthreads();
    }
    #pragma unroll
    for (int mt = 0; mt < 2; mt++)
        #pragma unroll
        for (int nt = 0; nt < 4; nt++)
            #pragma unroll
            for (int i = 0; i < 4; i++) {
                int r = row0 + m0 + mt * 16 + (lane >> 2) + ((i >= 2) ? 8 : 0);
                int cc = col0 + n0 + nt * 8 + (lane & 3) * 2 + (i & 1);
                out[(size_t)r * HID + cc] = c[mt][nt][i];
            }
}

// ---- K4: expert gate_up (gathered rows). 64x64 tiles ----
__global__ __launch_bounds__(256) void k_egu(
    const float* __restrict__ x,
    const float* __restrict__ t_gu, const float* __restrict__ v_gu)
{
    const int z = blockIdx.z;
    const int mod = z >> 4, e = z & 15;
    const int I = mod ? IV : IT;
    const int col0 = blockIdx.x * 64;
    if (col0 >= I) return;
    const int nq = g_cnt[z];
    const int row0 = blockIdx.y * 64;
    if (row0 >= nq) return;
    const float* W = mod ? (v_gu + (size_t)e * HID * 2 * IV)
                         : (t_gu + (size_t)e * HID * 2 * IT);
    const int ldw = 2 * I;

    __shared__ uint32_t As[64][BKP];
    __shared__ uint32_t Bg[64][BKP];
    __shared__ uint32_t Bu[64][BKP];
    __shared__ int toks[64];

    const int tid = threadIdx.x, wid = tid >> 5, lane = tid & 31;
    const int m0 = (wid >> 1) * 16, n0 = (wid & 1) * 32;
    const int ln = tid & 63, lk = (tid >> 6) * 8;
    if (tid < 64) {
        int s = row0 + tid;
        toks[tid] = (s < nq) ? g_tok[z][s] : 0;
    }
    __syncthreads();

    float cg[4][4] = {}, cu[4][4] = {};
    for (int k0 = 0; k0 < HID; k0 += BK) {
        #pragma unroll
        for (int p = 0; p < 2; p++) {
            int idx = tid + p * 256;
            int r = idx >> 3, c4 = (idx & 7) * 4;
            float4 v = *(const float4*)&x[(size_t)toks[r] * HID + k0 + c4];
            *(uint4*)&As[r][c4] = make_uint4(f2tf32(v.x), f2tf32(v.y), f2tf32(v.z), f2tf32(v.w));
        }
        uint32_t vg[8], vu[8];
        #pragma unroll
        for (int j = 0; j < 8; j++) {
            vg[j] = f2tf32(W[(size_t)(k0 + lk + j) * ldw + col0 + ln]);
            vu[j] = f2tf32(W[(size_t)(k0 + lk + j) * ldw + I + col0 + ln]);
        }
        *(uint4*)&Bg[ln][lk]     = make_uint4(vg[0], vg[1], vg[2], vg[3]);
        *(uint4*)&Bg[ln][lk + 4] = make_uint4(vg[4], vg[5], vg[6], vg[7]);
        *(uint4*)&Bu[ln][lk]     = make_uint4(vu[0], vu[1], vu[2], vu[3]);
        *(uint4*)&Bu[ln][lk + 4] = make_uint4(vu[4], vu[5], vu[6], vu[7]);
        __syncthreads();
        #pragma unroll
        for (int kk = 0; kk < 4; kk++) {
            const int kc = kk * 8;
            uint32_t a[4];
            int r = m0 + (lane >> 2);
            a[0] = As[r][kc + (lane & 3)];
            a[1] = As[r + 8][kc + (lane & 3)];
            a[2] = As[r][kc + (lane & 3) + 4];
            a[3] = As[r + 8][kc + (lane & 3) + 4];
            #pragma unroll
            for (int nt = 0; nt < 4; nt++) {
                int nb = n0 + nt * 8 + (lane >> 2);
                uint32_t g0 = Bg[nb][kc + (lane & 3)], g1 = Bg[nb][kc + (lane & 3) + 4];
                uint32_t u0 = Bu[nb][kc + (lane & 3)], u1 = Bu[nb][kc + (lane & 3) + 4];
                mma8(cg[nt], a, g0, g1);
                mma8(cu[nt], a, u0, u1);
            }
        }
        __syncthreads();
    }
    #pragma unroll
    for (int nt = 0; nt < 4; nt++)
        #pragma unroll
        for (int i = 0; i < 4; i++) {
            int slot = row0 + m0 + (lane >> 2) + ((i >= 2) ? 8 : 0);
            if (slot < nq) {
                int cc = col0 + n0 + nt * 8 + (lane & 3) * 2 + (i & 1);
                float g = cg[nt][i];
                g_act[z][slot][cc] = g / (1.f + __expf(-g)) * cu[nt][i];
            }
        }
}

// ---- K5: expert down, weighted atomic scatter. 64x64 tiles ----
__global__ __launch_bounds__(256) void k_edn(
    const float* __restrict__ t_dn, const float* __restrict__ v_dn,
    float* __restrict__ out)
{
    const int z = blockIdx.z;
    const int mod = z >> 4, e = z & 15;
    const int nq = g_cnt[z];
    const int row0 = blockIdx.y * 64;
    if (row0 >= nq) return;
    const int col0 = blockIdx.x * 64;
    const int I = mod ? IV : IT;
    const float* W = mod ? (v_dn + (size_t)e * IV * HID)
                         : (t_dn + (size_t)e * IT * HID);

    __shared__ uint32_t As[64][BKP];
    __shared__ uint32_t Bs[64][BKP];
    __shared__ int   toks[64];
    __shared__ float wgts[64];

    const int tid = threadIdx.x, wid = tid >> 5, lane = tid & 31;
    const int m0 = (wid >> 1) * 16, n0 = (wid & 1) * 32;
    const int ln = tid & 63, lk = (tid >> 6) * 8;
    if (tid < 64) {
        int s = row0 + tid;
        toks[tid] = (s < nq) ? g_tok[z][s] : 0;
        wgts[tid] = (s < nq) ? g_wgt[z][s] : 0.f;
    }
    __syncthreads();

    float c[4][4] = {};
    for (int k0 = 0; k0 < I; k0 += BK) {
        #pragma unroll
        for (int p = 0; p < 2; p++) {
            int idx = tid + p * 256;
            int r = idx >> 3, c4 = (idx & 7) * 4;
            float4 v = *(const float4*)&g_act[z][row0 + r][k0 + c4];
            *(uint4*)&As[r][c4] = make_uint4(f2tf32(v.x), f2tf32(v.y), f2tf32(v.z), f2tf32(v.w));
        }
        uint32_t vb[8];
        #pragma unroll
        for (int j = 0; j < 8; j++)
            vb[j] = f2tf32(W[(size_t)(k0 + lk + j) * HID + col0 + ln]);
        *(uint4*)&Bs[ln][lk]     = make_uint4(vb[0], vb[1], vb[2], vb[3]);
        *(uint4*)&Bs[ln][lk + 4] = make_uint4(vb[4], vb[5], vb[6], vb[7]);
        __syncthreads();
        #pragma unroll
        for (int kk = 0; kk < 4; kk++) {
            const int kc = kk * 8;
            uint32_t a[4];
            int r = m0 + (lane >> 2);
            a[0] = As[r][kc + (lane & 3)];
            a[1] = As[r + 8][kc + (lane & 3)];
            a[2] = As[r][kc + (lane & 3) + 4];
            a[3] = As[r + 8][kc + (lane & 3) + 4];
            #pragma unroll
            for (int nt = 0; nt < 4; nt++) {
                int nb = n0 + nt * 8 + (lane >> 2);
                uint32_t b0 = Bs[nb][kc + (lane & 3)], b1 = Bs[nb][kc + (lane & 3) + 4];
                mma8(c[nt], a, b0, b1);
            }
        }
        __syncthreads();
    }
    #pragma unroll
    for (int nt = 0; nt < 4; nt++)
        #pragma unroll
        for (int i = 0; i < 4; i++) {
            int ls = m0 + (lane >> 2) + ((i >= 2) ? 8 : 0);
            int slot = row0 + ls;
            if (slot < nq) {
                int cc = col0 + n0 + nt * 8 + (lane & 3) * 2 + (i & 1);
                atomicAdd(&out[(size_t)toks[ls] * HID + cc], wgts[ls] * c[nt][i]);
            }
        }
}

// ---------------- launch ----------------
extern "C" void kernel_launch(void* const* d_in, const int* in_sizes, int n_in,
                              void* d_out, int out_size)
{
    const float* x   = (const float*)d_in[0];
    const int*   tt  = (const int*)d_in[1];
    const float* trw = (const float*)d_in[2];
    const float* tb  = (const float*)d_in[3];
    const float* tgu = (const float*)d_in[4];
    const float* tdn = (const float*)d_in[5];
    const float* vrw = (const float*)d_in[6];
    const float* vb  = (const float*)d_in[7];
    const float* vgu = (const float*)d_in[8];
    const float* vdn = (const float*)d_in[9];
    const float* sg  = (const float*)d_in[10];
    const float* su  = (const float*)d_in[11];
    const float* sd  = (const float*)d_in[12];

    float* out        = (float*)d_out;
    float* out_logits = out + (size_t)NT * HID;

    k_zero<<<1, 32>>>();
    k_router<<<NT, 512>>>(x, tt, trw, tb, vrw, vb, out_logits);
    k_sgu<<<dim3(16, 8), 256>>>(x, sg, su);
    k_sdn<<<dim3(16, 8), 256>>>(sd, out);
    k_egu<<<dim3(8, 16, NZ), 256>>>(x, tgu, vgu);
    k_edn<<<dim3(16, 16, NZ), 256>>>(tdn, vdn, out);
}